// round 3
// baseline (speedup 1.0000x reference)
#include <cuda_runtime.h>
#include <cuda_fp16.h>
#include <cstdint>

#define N_TOK 8192
#define D_IN  4096
#define D_OUT 4096
#define RANK  64

#define BM 128
#define BN 128
#define BK 64
#define NCHUNK (D_IN / BK)   // 64
#define STAGES 4
#define THREADS 256

#define TILE_BYTES (BM * BK * 2)            // 16384 (A); B same
#define STAGE_BYTES (2 * TILE_BYTES)        // 32768
#define SMEM_TOTAL (STAGES * STAGE_BYTES)   // 131072

// Scratch via __device__ globals (runtime allocation is forbidden)
__device__ __half g_A[(size_t)N_TOK * D_IN];   // fp16(x)           64 MB
__device__ __half g_B[(size_t)D_OUT * D_IN];   // fp16(Q*s + U@D)   32 MB

// ---------------- PTX helpers ----------------
__device__ __forceinline__ uint32_t smem_u32(const void* p) {
    uint32_t a;
    asm("{ .reg .u64 t; cvta.to.shared.u64 t, %1; cvt.u32.u64 %0, t; }" : "=r"(a) : "l"(p));
    return a;
}
__device__ __forceinline__ void cp16(uint32_t saddr, const void* g) {
    asm volatile("cp.async.cg.shared.global [%0], [%1], 16;" :: "r"(saddr), "l"(g));
}
#define CP_COMMIT() asm volatile("cp.async.commit_group;" ::: "memory")
#define CP_WAIT2()  asm volatile("cp.async.wait_group 2;" ::: "memory")

__device__ __forceinline__ void ldm_x4(uint32_t& r0, uint32_t& r1, uint32_t& r2, uint32_t& r3,
                                       uint32_t addr) {
    asm volatile("ldmatrix.sync.aligned.m8n8.x4.shared.b16 {%0,%1,%2,%3}, [%4];"
                 : "=r"(r0), "=r"(r1), "=r"(r2), "=r"(r3) : "r"(addr));
}
__device__ __forceinline__ void mma16816(float* d, const uint32_t* a, const uint32_t* b) {
    asm volatile(
        "mma.sync.aligned.m16n8k16.row.col.f32.f16.f16.f32 "
        "{%0,%1,%2,%3}, {%4,%5,%6,%7}, {%8,%9}, {%0,%1,%2,%3};"
        : "+f"(d[0]), "+f"(d[1]), "+f"(d[2]), "+f"(d[3])
        : "r"(a[0]), "r"(a[1]), "r"(a[2]), "r"(a[3]), "r"(b[0]), "r"(b[1]));
}

// ---------------- prep kernels ----------------

// x (fp32) -> g_A (fp16); 8 floats / thread
__global__ void __launch_bounds__(256) prep_a_kernel(const float* __restrict__ x) {
    size_t i = (size_t)blockIdx.x * 2048 + (size_t)threadIdx.x * 8;
    float4 v0 = *reinterpret_cast<const float4*>(x + i);
    float4 v1 = *reinterpret_cast<const float4*>(x + i + 4);
    __half2 hv[4];
    hv[0] = __floats2half2_rn(v0.x, v0.y);
    hv[1] = __floats2half2_rn(v0.z, v0.w);
    hv[2] = __floats2half2_rn(v1.x, v1.y);
    hv[3] = __floats2half2_rn(v1.z, v1.w);
    *reinterpret_cast<uint4*>(g_A + i) = *reinterpret_cast<uint4*>(hv);
}

// W_tot[o,i] = Q[o,i]*scales[o] + sum_r U[o,r]*D[r,i]  -> g_B (fp16)
__global__ void __launch_bounds__(256) prep_w_kernel(
    const float* __restrict__ scales, const float* __restrict__ U,
    const float* __restrict__ Dm, const int* __restrict__ Q)
{
    __shared__ float Us[64][65];  // [o][r]
    __shared__ float Ds[64][68];  // [r][i]
    int i0 = blockIdx.x * 64;
    int o0 = blockIdx.y * 64;
    int tid = threadIdx.x;

    for (int j = tid; j < 4096; j += 256) {
        int r = j >> 6, c = j & 63;
        Us[r][c] = U[(size_t)(o0 + r) * RANK + c];
        Ds[r][c] = Dm[(size_t)r * D_IN + i0 + c];
    }
    __syncthreads();

    int tx = tid & 15, ty = tid >> 4;
    float acc[4][4] = {};
#pragma unroll
    for (int r = 0; r < 64; ++r) {
        float a[4];
        float4 b4 = *reinterpret_cast<const float4*>(&Ds[r][tx * 4]);
        float b[4] = {b4.x, b4.y, b4.z, b4.w};
#pragma unroll
        for (int p = 0; p < 4; ++p) a[p] = Us[ty * 4 + p][r];
#pragma unroll
        for (int p = 0; p < 4; ++p)
#pragma unroll
            for (int q = 0; q < 4; ++q) acc[p][q] = fmaf(a[p], b[q], acc[p][q]);
    }

#pragma unroll
    for (int p = 0; p < 4; ++p) {
        int o = o0 + ty * 4 + p;
        float sc = scales[o];
        int4 q4 = *reinterpret_cast<const int4*>(Q + (size_t)o * D_IN + i0 + tx * 4);
        __half2 h0 = __floats2half2_rn(fmaf((float)q4.x, sc, acc[p][0]),
                                       fmaf((float)q4.y, sc, acc[p][1]));
        __half2 h1 = __floats2half2_rn(fmaf((float)q4.z, sc, acc[p][2]),
                                       fmaf((float)q4.w, sc, acc[p][3]));
        uint2 st;
        st.x = *reinterpret_cast<uint32_t*>(&h0);
        st.y = *reinterpret_cast<uint32_t*>(&h1);
        *reinterpret_cast<uint2*>(g_B + (size_t)o * D_IN + i0 + tx * 4) = st;
    }
}

// ---------------- main GEMM ----------------
// out[m,n] = sum_k g_A[m,k] * g_B[n,k]; fp16 in, fp32 accum.
// BM=BN=128, BK=64, 4-stage cp.async, mma.sync m16n8k16.
__global__ void __launch_bounds__(THREADS, 1) gemm_kernel(float* __restrict__ out) {
    extern __shared__ char smem[];
    uint32_t sbase = smem_u32(smem);
    int tid = threadIdx.x;
    int wid = tid >> 5;
    int lane = tid & 31;

    // Raster: bands of 16 m-tiles x all 32 n-tiles (A slice 16MB + W 32MB < L2)
    int bx = blockIdx.x;
    int band = bx >> 9;                 // 0..3
    int r = bx & 511;
    int n_tile = (r >> 4);              // 0..31
    int m_tile = (band << 4) + (r & 15);
    int m0 = m_tile * BM;
    int n0 = n_tile * BN;

    // Warp tile: wm in {0,1}, wn in {0..3}; 64x32 per warp
    int wm = wid & 1;
    int wn = wid >> 1;

    const __half* gA = g_A;
    const __half* gB = g_B;

    // ---- stage loader (cp.async, swizzled) ----
    auto load_stage = [&](int s, int c) {
        uint32_t st = sbase + s * STAGE_BYTES;
        int k0 = c * BK;
#pragma unroll
        for (int j = 0; j < 4; ++j) {
            int t = tid + j * 256;
            int row = t >> 3, seg = t & 7;
            uint32_t so = (uint32_t)(row * 128 + ((seg ^ (row & 7)) << 4));
            cp16(st + so, gA + (size_t)(m0 + row) * D_IN + k0 + seg * 8);
        }
#pragma unroll
        for (int j = 0; j < 4; ++j) {
            int t = tid + j * 256;
            int row = t >> 3, seg = t & 7;
            uint32_t so = (uint32_t)(row * 128 + ((seg ^ (row & 7)) << 4));
            cp16(st + TILE_BYTES + so, gB + (size_t)(n0 + row) * D_IN + k0 + seg * 8);
        }
    };

    // Prologue: stages 0..2
#pragma unroll
    for (int s = 0; s < STAGES - 1; ++s) {
        load_stage(s, s);
        CP_COMMIT();
    }

    float acc[4][4][4] = {};  // [mi][ni][4]

    // ldmatrix base rows for this warp
    int a_row_base = wm * 64 + (lane & 15);
    int b_row_base = wn * 32 + (lane & 15);
    int hi = lane >> 4;  // chunk select within k16

    for (int c = 0; c < NCHUNK; ++c) {
        CP_WAIT2();
        __syncthreads();

        if (c + STAGES - 1 < NCHUNK) load_stage((c + STAGES - 1) & (STAGES - 1), c + STAGES - 1);
        CP_COMMIT();

        uint32_t stA = sbase + (c & (STAGES - 1)) * STAGE_BYTES;
        uint32_t stB = stA + TILE_BYTES;

#pragma unroll
        for (int kt = 0; kt < 4; ++kt) {
            // A fragments: 4 m-tiles, each ldmatrix.x4 (m16 x k16)
            uint32_t af[4][4];
#pragma unroll
            for (int mi = 0; mi < 4; ++mi) {
                int row = a_row_base + mi * 16;
                uint32_t chunk = (uint32_t)((kt * 2 + hi) ^ (row & 7));
                uint32_t addr = stA + (uint32_t)row * 128 + (chunk << 4);
                ldm_x4(af[mi][0], af[mi][1], af[mi][2], af[mi][3], addr);
            }
            // B fragments: 4 n-tiles; one x4 covers two n8-tiles
            uint32_t bf[4][2];
#pragma unroll
            for (int nj = 0; nj < 2; ++nj) {
                int row = b_row_base + nj * 16;
                uint32_t chunk = (uint32_t)((kt * 2 + hi) ^ (row & 7));
                uint32_t addr = stB + (uint32_t)row * 128 + (chunk << 4);
                uint32_t r0, r1, r2, r3;
                ldm_x4(r0, r1, r2, r3, addr);
                bf[nj * 2][0] = r0; bf[nj * 2][1] = r2;
                bf[nj * 2 + 1][0] = r1; bf[nj * 2 + 1][1] = r3;
            }
#pragma unroll
            for (int mi = 0; mi < 4; ++mi)
#pragma unroll
                for (int ni = 0; ni < 4; ++ni)
                    mma16816(acc[mi][ni], af[mi], bf[ni]);
        }
    }

    // Epilogue: direct float2 stores
    {
        int row0 = m0 + wm * 64 + (lane >> 2);
        int colb = n0 + wn * 32 + (lane & 3) * 2;
#pragma unroll
        for (int mi = 0; mi < 4; ++mi) {
#pragma unroll
            for (int ni = 0; ni < 4; ++ni) {
                float* p0 = out + (size_t)(row0 + mi * 16) * D_OUT + colb + ni * 8;
                float* p1 = out + (size_t)(row0 + mi * 16 + 8) * D_OUT + colb + ni * 8;
                float2 v0 = {acc[mi][ni][0], acc[mi][ni][1]};
                float2 v1 = {acc[mi][ni][2], acc[mi][ni][3]};
                *reinterpret_cast<float2*>(p0) = v0;
                *reinterpret_cast<float2*>(p1) = v1;
            }
        }
    }
}

// ---------------- launch ----------------
extern "C" void kernel_launch(void* const* d_in, const int* in_sizes, int n_in,
                              void* d_out, int out_size) {
    const float* x      = (const float*)d_in[0];
    const float* scales = (const float*)d_in[1];
    const float* U      = (const float*)d_in[2];
    const float* Dm     = (const float*)d_in[3];
    const int*   Q      = (const int*)d_in[4];
    float* out = (float*)d_out;

    cudaFuncSetAttribute(gemm_kernel, cudaFuncAttributeMaxDynamicSharedMemorySize, SMEM_TOTAL);

    prep_a_kernel<<<(int)((N_TOK * (size_t)D_IN) / 2048), 256>>>(x);
    prep_w_kernel<<<dim3(D_IN / 64, D_OUT / 64), 256>>>(scales, U, Dm, Q);
    gemm_kernel<<<(N_TOK / BM) * (D_OUT / BN), THREADS, SMEM_TOTAL>>>(out);
}

// round 5
// speedup vs baseline: 1.1130x; 1.1130x over previous
#include <cuda_runtime.h>
#include <cuda_fp16.h>
#include <cstdint>

#define N_TOK 8192
#define D_IN  4096
#define D_OUT 4096
#define RANK  64

#define BM 128
#define BN 256
#define BK 64
#define NCHUNK (D_IN / BK)   // 64
#define STAGES 4
#define THREADS 256

#define A_TILE_BYTES (BM * BK * 2)          // 16384
#define B_TILE_BYTES (BN * BK * 2)          // 32768
#define STAGE_BYTES (A_TILE_BYTES + B_TILE_BYTES)  // 49152
#define SMEM_TOTAL (STAGES * STAGE_BYTES)   // 196608

// Scratch via __device__ globals (runtime allocation is forbidden)
__device__ __half g_A[(size_t)N_TOK * D_IN];   // fp16(x)           64 MB
__device__ __half g_B[(size_t)D_OUT * D_IN];   // fp16(Q*s + U@D)   32 MB

// ---------------- PTX helpers ----------------
__device__ __forceinline__ uint32_t smem_u32(const void* p) {
    uint32_t a;
    asm("{ .reg .u64 t; cvta.to.shared.u64 t, %1; cvt.u32.u64 %0, t; }" : "=r"(a) : "l"(p));
    return a;
}
__device__ __forceinline__ void cp16(uint32_t saddr, const void* g) {
    asm volatile("cp.async.cg.shared.global [%0], [%1], 16;" :: "r"(saddr), "l"(g));
}
#define CP_COMMIT() asm volatile("cp.async.commit_group;" ::: "memory")
#define CP_WAIT2()  asm volatile("cp.async.wait_group 2;" ::: "memory")

__device__ __forceinline__ void ldm_x4(uint32_t& r0, uint32_t& r1, uint32_t& r2, uint32_t& r3,
                                       uint32_t addr) {
    asm volatile("ldmatrix.sync.aligned.m8n8.x4.shared.b16 {%0,%1,%2,%3}, [%4];"
                 : "=r"(r0), "=r"(r1), "=r"(r2), "=r"(r3) : "r"(addr));
}
__device__ __forceinline__ void mma16816(float* d, const uint32_t* a, const uint32_t* b) {
    asm volatile(
        "mma.sync.aligned.m16n8k16.row.col.f32.f16.f16.f32 "
        "{%0,%1,%2,%3}, {%4,%5,%6,%7}, {%8,%9}, {%0,%1,%2,%3};"
        : "+f"(d[0]), "+f"(d[1]), "+f"(d[2]), "+f"(d[3])
        : "r"(a[0]), "r"(a[1]), "r"(a[2]), "r"(a[3]), "r"(b[0]), "r"(b[1]));
}

// ---------------- prep kernels ----------------

// x (fp32) -> g_A (fp16); 8 floats / thread
__global__ void __launch_bounds__(256) prep_a_kernel(const float* __restrict__ x) {
    size_t i = (size_t)blockIdx.x * 2048 + (size_t)threadIdx.x * 8;
    float4 v0 = *reinterpret_cast<const float4*>(x + i);
    float4 v1 = *reinterpret_cast<const float4*>(x + i + 4);
    __half2 hv[4];
    hv[0] = __floats2half2_rn(v0.x, v0.y);
    hv[1] = __floats2half2_rn(v0.z, v0.w);
    hv[2] = __floats2half2_rn(v1.x, v1.y);
    hv[3] = __floats2half2_rn(v1.z, v1.w);
    *reinterpret_cast<uint4*>(g_A + i) = *reinterpret_cast<uint4*>(hv);
}

// W_tot[o,i] = Q[o,i]*scales[o] + sum_r U[o,r]*D[r,i]  -> g_B (fp16)
__global__ void __launch_bounds__(256) prep_w_kernel(
    const float* __restrict__ scales, const float* __restrict__ U,
    const float* __restrict__ Dm, const int* __restrict__ Q)
{
    __shared__ float Us[64][65];  // [o][r]
    __shared__ float Ds[64][68];  // [r][i]
    int i0 = blockIdx.x * 64;
    int o0 = blockIdx.y * 64;
    int tid = threadIdx.x;

    for (int j = tid; j < 4096; j += 256) {
        int r = j >> 6, c = j & 63;
        Us[r][c] = U[(size_t)(o0 + r) * RANK + c];
        Ds[r][c] = Dm[(size_t)r * D_IN + i0 + c];
    }
    __syncthreads();

    int tx = tid & 15, ty = tid >> 4;
    float acc[4][4] = {};
#pragma unroll
    for (int r = 0; r < 64; ++r) {
        float a[4];
        float4 b4 = *reinterpret_cast<const float4*>(&Ds[r][tx * 4]);
        float b[4] = {b4.x, b4.y, b4.z, b4.w};
#pragma unroll
        for (int p = 0; p < 4; ++p) a[p] = Us[ty * 4 + p][r];
#pragma unroll
        for (int p = 0; p < 4; ++p)
#pragma unroll
            for (int q = 0; q < 4; ++q) acc[p][q] = fmaf(a[p], b[q], acc[p][q]);
    }

#pragma unroll
    for (int p = 0; p < 4; ++p) {
        int o = o0 + ty * 4 + p;
        float sc = scales[o];
        int4 q4 = *reinterpret_cast<const int4*>(Q + (size_t)o * D_IN + i0 + tx * 4);
        __half2 h0 = __floats2half2_rn(fmaf((float)q4.x, sc, acc[p][0]),
                                       fmaf((float)q4.y, sc, acc[p][1]));
        __half2 h1 = __floats2half2_rn(fmaf((float)q4.z, sc, acc[p][2]),
                                       fmaf((float)q4.w, sc, acc[p][3]));
        uint2 st;
        st.x = *reinterpret_cast<uint32_t*>(&h0);
        st.y = *reinterpret_cast<uint32_t*>(&h1);
        *reinterpret_cast<uint2*>(g_B + (size_t)o * D_IN + i0 + tx * 4) = st;
    }
}

// ---------------- main GEMM ----------------
// out[m,n] = sum_k g_A[m,k] * g_B[n,k]; fp16 in, fp32 accum.
// BM=128, BN=256, BK=64, 4-stage cp.async, mma.sync m16n8k16.
// 8 warps in 2x4; each warp owns a 64x64 tile (4 m16-tiles x 8 n8-tiles).
__global__ void __launch_bounds__(THREADS, 1) gemm_kernel(float* __restrict__ out) {
    extern __shared__ char smem[];
    uint32_t sbase = smem_u32(smem);
    int tid = threadIdx.x;
    int wid = tid >> 5;
    int lane = tid & 31;

    // Raster: 4 bands of 16 m-tiles x 16 n-tiles (A band 16MB + W 32MB < L2)
    int bx = blockIdx.x;
    int band = bx >> 8;                  // 0..3
    int r = bx & 255;
    int n_tile = r >> 4;                 // 0..15
    int m_tile = (band << 4) + (r & 15); // 0..63
    int m0 = m_tile * BM;
    int n0 = n_tile * BN;

    // Warp tile: wm in {0,1} (64 rows), wn in {0..3} (64 cols)
    int wm = wid & 1;
    int wn = wid >> 1;

    const __half* gA = g_A;
    const __half* gB = g_B;

    // ---- stage loader (cp.async, swizzled 128B rows) ----
    auto load_stage = [&](int s, int c) {
        uint32_t st = sbase + s * STAGE_BYTES;
        int k0 = c * BK;
#pragma unroll
        for (int j = 0; j < 4; ++j) {  // A: 1024 chunks
            int t = tid + j * 256;
            int row = t >> 3, seg = t & 7;
            uint32_t so = (uint32_t)(row * 128 + ((seg ^ (row & 7)) << 4));
            cp16(st + so, gA + (size_t)(m0 + row) * D_IN + k0 + seg * 8);
        }
#pragma unroll
        for (int j = 0; j < 8; ++j) {  // B: 2048 chunks
            int t = tid + j * 256;
            int row = t >> 3, seg = t & 7;
            uint32_t so = (uint32_t)(row * 128 + ((seg ^ (row & 7)) << 4));
            cp16(st + A_TILE_BYTES + so, gB + (size_t)(n0 + row) * D_IN + k0 + seg * 8);
        }
    };

    // Prologue: stages 0..2
#pragma unroll
    for (int s = 0; s < STAGES - 1; ++s) {
        load_stage(s, s);
        CP_COMMIT();
    }

    float acc[4][8][4] = {};  // [mi][ni][4]

    int a_row_base = wm * 64 + (lane & 15);
    int b_row_base = wn * 64 + (lane & 15);
    int hi = lane >> 4;  // k16-half select

    for (int c = 0; c < NCHUNK; ++c) {
        CP_WAIT2();
        __syncthreads();

        if (c + STAGES - 1 < NCHUNK) load_stage((c + STAGES - 1) & (STAGES - 1), c + STAGES - 1);
        CP_COMMIT();

        uint32_t stA = sbase + (c & (STAGES - 1)) * STAGE_BYTES;
        uint32_t stB = stA + A_TILE_BYTES;

#pragma unroll
        for (int kt = 0; kt < 4; ++kt) {
            // A fragments: 4 m16-tiles
            uint32_t af[4][4];
#pragma unroll
            for (int mi = 0; mi < 4; ++mi) {
                int row = a_row_base + mi * 16;
                uint32_t chunk = (uint32_t)((kt * 2 + hi) ^ (row & 7));
                uint32_t addr = stA + (uint32_t)row * 128 + (chunk << 4);
                ldm_x4(af[mi][0], af[mi][1], af[mi][2], af[mi][3], addr);
            }
            // B fragments: 8 n8-tiles via 4 x4-loads
            uint32_t bf[8][2];
#pragma unroll
            for (int nj = 0; nj < 4; ++nj) {
                int row = b_row_base + nj * 16;
                uint32_t chunk = (uint32_t)((kt * 2 + hi) ^ (row & 7));
                uint32_t addr = stB + (uint32_t)row * 128 + (chunk << 4);
                uint32_t r0, r1, r2, r3;
                ldm_x4(r0, r1, r2, r3, addr);
                bf[nj * 2][0] = r0; bf[nj * 2][1] = r2;
                bf[nj * 2 + 1][0] = r1; bf[nj * 2 + 1][1] = r3;
            }
#pragma unroll
            for (int mi = 0; mi < 4; ++mi)
#pragma unroll
                for (int ni = 0; ni < 8; ++ni)
                    mma16816(acc[mi][ni], af[mi], bf[ni]);
        }
    }

    // Epilogue: direct float2 stores
    {
        int row0 = m0 + wm * 64 + (lane >> 2);
        int colb = n0 + wn * 64 + (lane & 3) * 2;
#pragma unroll
        for (int mi = 0; mi < 4; ++mi) {
#pragma unroll
            for (int ni = 0; ni < 8; ++ni) {
                float* p0 = out + (size_t)(row0 + mi * 16) * D_OUT + colb + ni * 8;
                float* p1 = out + (size_t)(row0 + mi * 16 + 8) * D_OUT + colb + ni * 8;
                float2 v0 = {acc[mi][ni][0], acc[mi][ni][1]};
                float2 v1 = {acc[mi][ni][2], acc[mi][ni][3]};
                *reinterpret_cast<float2*>(p0) = v0;
                *reinterpret_cast<float2*>(p1) = v1;
            }
        }
    }
}

// ---------------- launch ----------------
extern "C" void kernel_launch(void* const* d_in, const int* in_sizes, int n_in,
                              void* d_out, int out_size) {
    const float* x      = (const float*)d_in[0];
    const float* scales = (const float*)d_in[1];
    const float* U      = (const float*)d_in[2];
    const float* Dm     = (const float*)d_in[3];
    const int*   Q      = (const int*)d_in[4];
    float* out = (float*)d_out;

    cudaFuncSetAttribute(gemm_kernel, cudaFuncAttributeMaxDynamicSharedMemorySize, SMEM_TOTAL);

    prep_a_kernel<<<(int)((N_TOK * (size_t)D_IN) / 2048), 256>>>(x);
    prep_w_kernel<<<dim3(D_IN / 64, D_OUT / 64), 256>>>(scales, U, Dm, Q);
    gemm_kernel<<<(N_TOK / BM) * (D_OUT / BN), THREADS, SMEM_TOTAL>>>(out);
}

// round 6
// speedup vs baseline: 1.1320x; 1.0171x over previous
#include <cuda_runtime.h>
#include <cuda_fp16.h>
#include <cstdint>

#define N_TOK 8192
#define D_IN  4096
#define D_OUT 4096
#define RANK  64

#define BM 128
#define BN 256
#define BK 64
#define NCHUNK (D_IN / BK)   // 64
#define STAGES 4
#define THREADS 512

#define A_TILE_BYTES (BM * BK * 2)          // 16384
#define B_TILE_BYTES (BN * BK * 2)          // 32768
#define STAGE_BYTES (A_TILE_BYTES + B_TILE_BYTES)  // 49152
#define SMEM_TOTAL (STAGES * STAGE_BYTES)   // 196608

// Scratch via __device__ globals (runtime allocation is forbidden)
__device__ __half g_A[(size_t)N_TOK * D_IN];   // fp16(x)           64 MB
__device__ __half g_B[(size_t)D_OUT * D_IN];   // fp16(Q*s + U@D)   32 MB

// ---------------- PTX helpers ----------------
__device__ __forceinline__ uint32_t smem_u32(const void* p) {
    uint32_t a;
    asm("{ .reg .u64 t; cvta.to.shared.u64 t, %1; cvt.u32.u64 %0, t; }" : "=r"(a) : "l"(p));
    return a;
}
__device__ __forceinline__ void cp16(uint32_t saddr, const void* g) {
    asm volatile("cp.async.cg.shared.global [%0], [%1], 16;" :: "r"(saddr), "l"(g));
}
#define CP_COMMIT() asm volatile("cp.async.commit_group;" ::: "memory")
#define CP_WAIT2()  asm volatile("cp.async.wait_group 2;" ::: "memory")

__device__ __forceinline__ void ldm_x4(uint32_t& r0, uint32_t& r1, uint32_t& r2, uint32_t& r3,
                                       uint32_t addr) {
    asm volatile("ldmatrix.sync.aligned.m8n8.x4.shared.b16 {%0,%1,%2,%3}, [%4];"
                 : "=r"(r0), "=r"(r1), "=r"(r2), "=r"(r3) : "r"(addr));
}
__device__ __forceinline__ void mma16816(float* d, const uint32_t* a, const uint32_t* b) {
    asm volatile(
        "mma.sync.aligned.m16n8k16.row.col.f32.f16.f16.f32 "
        "{%0,%1,%2,%3}, {%4,%5,%6,%7}, {%8,%9}, {%0,%1,%2,%3};"
        : "+f"(d[0]), "+f"(d[1]), "+f"(d[2]), "+f"(d[3])
        : "r"(a[0]), "r"(a[1]), "r"(a[2]), "r"(a[3]), "r"(b[0]), "r"(b[1]));
}

// ---------------- prep kernels ----------------

// x (fp32) -> g_A (fp16); 8 floats / thread
__global__ void __launch_bounds__(256) prep_a_kernel(const float* __restrict__ x) {
    size_t i = (size_t)blockIdx.x * 2048 + (size_t)threadIdx.x * 8;
    float4 v0 = *reinterpret_cast<const float4*>(x + i);
    float4 v1 = *reinterpret_cast<const float4*>(x + i + 4);
    __half2 hv[4];
    hv[0] = __floats2half2_rn(v0.x, v0.y);
    hv[1] = __floats2half2_rn(v0.z, v0.w);
    hv[2] = __floats2half2_rn(v1.x, v1.y);
    hv[3] = __floats2half2_rn(v1.z, v1.w);
    *reinterpret_cast<uint4*>(g_A + i) = *reinterpret_cast<uint4*>(hv);
}

// W_tot[o,i] = Q[o,i]*scales[o] + sum_r U[o,r]*D[r,i]  -> g_B (fp16)
__global__ void __launch_bounds__(256) prep_w_kernel(
    const float* __restrict__ scales, const float* __restrict__ U,
    const float* __restrict__ Dm, const int* __restrict__ Q)
{
    __shared__ float Us[64][65];  // [o][r]
    __shared__ float Ds[64][68];  // [r][i]
    int i0 = blockIdx.x * 64;
    int o0 = blockIdx.y * 64;
    int tid = threadIdx.x;

    for (int j = tid; j < 4096; j += 256) {
        int r = j >> 6, c = j & 63;
        Us[r][c] = U[(size_t)(o0 + r) * RANK + c];
        Ds[r][c] = Dm[(size_t)r * D_IN + i0 + c];
    }
    __syncthreads();

    int tx = tid & 15, ty = tid >> 4;
    float acc[4][4] = {};
#pragma unroll
    for (int r = 0; r < 64; ++r) {
        float a[4];
        float4 b4 = *reinterpret_cast<const float4*>(&Ds[r][tx * 4]);
        float b[4] = {b4.x, b4.y, b4.z, b4.w};
#pragma unroll
        for (int p = 0; p < 4; ++p) a[p] = Us[ty * 4 + p][r];
#pragma unroll
        for (int p = 0; p < 4; ++p)
#pragma unroll
            for (int q = 0; q < 4; ++q) acc[p][q] = fmaf(a[p], b[q], acc[p][q]);
    }

#pragma unroll
    for (int p = 0; p < 4; ++p) {
        int o = o0 + ty * 4 + p;
        float sc = scales[o];
        int4 q4 = *reinterpret_cast<const int4*>(Q + (size_t)o * D_IN + i0 + tx * 4);
        __half2 h0 = __floats2half2_rn(fmaf((float)q4.x, sc, acc[p][0]),
                                       fmaf((float)q4.y, sc, acc[p][1]));
        __half2 h1 = __floats2half2_rn(fmaf((float)q4.z, sc, acc[p][2]),
                                       fmaf((float)q4.w, sc, acc[p][3]));
        uint2 st;
        st.x = *reinterpret_cast<uint32_t*>(&h0);
        st.y = *reinterpret_cast<uint32_t*>(&h1);
        *reinterpret_cast<uint2*>(g_B + (size_t)o * D_IN + i0 + tx * 4) = st;
    }
}

// ---------------- main GEMM ----------------
// out[m,n] = sum_k g_A[m,k] * g_B[n,k]; fp16 in, fp32 accum.
// BM=128, BN=256, BK=64, 4-stage cp.async, mma.sync m16n8k16.
// 16 warps in 4x4; each warp owns a 32x64 tile (2 m16-tiles x 8 n8-tiles).
__global__ void __launch_bounds__(THREADS, 1) gemm_kernel(float* __restrict__ out) {
    extern __shared__ char smem[];
    uint32_t sbase = smem_u32(smem);
    int tid = threadIdx.x;
    int wid = tid >> 5;
    int lane = tid & 31;

    // Raster: 4 bands of 16 m-tiles x 16 n-tiles (A band 16MB + W 32MB < L2)
    int bx = blockIdx.x;
    int band = bx >> 8;                  // 0..3
    int r = bx & 255;
    int n_tile = r >> 4;                 // 0..15
    int m_tile = (band << 4) + (r & 15); // 0..63
    int m0 = m_tile * BM;
    int n0 = n_tile * BN;

    // Warp tile: wm in {0..3} (32 rows), wn in {0..3} (64 cols)
    int wm = wid & 3;
    int wn = wid >> 2;

    const __half* gA = g_A;
    const __half* gB = g_B;

    // ---- stage loader (cp.async, swizzled 128B rows) ----
    auto load_stage = [&](int s, int c) {
        uint32_t st = sbase + s * STAGE_BYTES;
        int k0 = c * BK;
#pragma unroll
        for (int j = 0; j < 2; ++j) {  // A: 1024 chunks
            int t = tid + j * THREADS;
            int row = t >> 3, seg = t & 7;
            uint32_t so = (uint32_t)(row * 128 + ((seg ^ (row & 7)) << 4));
            cp16(st + so, gA + (size_t)(m0 + row) * D_IN + k0 + seg * 8);
        }
#pragma unroll
        for (int j = 0; j < 4; ++j) {  // B: 2048 chunks
            int t = tid + j * THREADS;
            int row = t >> 3, seg = t & 7;
            uint32_t so = (uint32_t)(row * 128 + ((seg ^ (row & 7)) << 4));
            cp16(st + A_TILE_BYTES + so, gB + (size_t)(n0 + row) * D_IN + k0 + seg * 8);
        }
    };

    // Prologue: stages 0..2
#pragma unroll
    for (int s = 0; s < STAGES - 1; ++s) {
        load_stage(s, s);
        CP_COMMIT();
    }

    float acc[2][8][4] = {};  // [mi][ni][4]

    int a_row_base = wm * 32 + (lane & 15);
    int b_row_base = wn * 64 + (lane & 15);
    int hi = lane >> 4;  // k16-half select

    for (int c = 0; c < NCHUNK; ++c) {
        CP_WAIT2();
        __syncthreads();

        if (c + STAGES - 1 < NCHUNK) load_stage((c + STAGES - 1) & (STAGES - 1), c + STAGES - 1);
        CP_COMMIT();

        uint32_t stA = sbase + (c & (STAGES - 1)) * STAGE_BYTES;
        uint32_t stB = stA + A_TILE_BYTES;

#pragma unroll
        for (int kt = 0; kt < 4; ++kt) {
            // A fragments: 2 m16-tiles
            uint32_t af[2][4];
#pragma unroll
            for (int mi = 0; mi < 2; ++mi) {
                int row = a_row_base + mi * 16;
                uint32_t chunk = (uint32_t)((kt * 2 + hi) ^ (row & 7));
                uint32_t addr = stA + (uint32_t)row * 128 + (chunk << 4);
                ldm_x4(af[mi][0], af[mi][1], af[mi][2], af[mi][3], addr);
            }
            // B fragments: 8 n8-tiles via 4 x4-loads
            uint32_t bf[8][2];
#pragma unroll
            for (int nj = 0; nj < 4; ++nj) {
                int row = b_row_base + nj * 16;
                uint32_t chunk = (uint32_t)((kt * 2 + hi) ^ (row & 7));
                uint32_t addr = stB + (uint32_t)row * 128 + (chunk << 4);
                uint32_t r0, r1, r2, r3;
                ldm_x4(r0, r1, r2, r3, addr);
                bf[nj * 2][0] = r0; bf[nj * 2][1] = r2;
                bf[nj * 2 + 1][0] = r1; bf[nj * 2 + 1][1] = r3;
            }
#pragma unroll
            for (int mi = 0; mi < 2; ++mi)
#pragma unroll
                for (int ni = 0; ni < 8; ++ni)
                    mma16816(acc[mi][ni], af[mi], bf[ni]);
        }
    }

    // Epilogue: direct float2 stores
    {
        int row0 = m0 + wm * 32 + (lane >> 2);
        int colb = n0 + wn * 64 + (lane & 3) * 2;
#pragma unroll
        for (int mi = 0; mi < 2; ++mi) {
#pragma unroll
            for (int ni = 0; ni < 8; ++ni) {
                float* p0 = out + (size_t)(row0 + mi * 16) * D_OUT + colb + ni * 8;
                float* p1 = out + (size_t)(row0 + mi * 16 + 8) * D_OUT + colb + ni * 8;
                float2 v0 = {acc[mi][ni][0], acc[mi][ni][1]};
                float2 v1 = {acc[mi][ni][2], acc[mi][ni][3]};
                *reinterpret_cast<float2*>(p0) = v0;
                *reinterpret_cast<float2*>(p1) = v1;
            }
        }
    }
}

// ---------------- launch ----------------
extern "C" void kernel_launch(void* const* d_in, const int* in_sizes, int n_in,
                              void* d_out, int out_size) {
    const float* x      = (const float*)d_in[0];
    const float* scales = (const float*)d_in[1];
    const float* U      = (const float*)d_in[2];
    const float* Dm     = (const float*)d_in[3];
    const int*   Q      = (const int*)d_in[4];
    float* out = (float*)d_out;

    cudaFuncSetAttribute(gemm_kernel, cudaFuncAttributeMaxDynamicSharedMemorySize, SMEM_TOTAL);

    prep_a_kernel<<<(int)((N_TOK * (size_t)D_IN) / 2048), 256>>>(x);
    prep_w_kernel<<<dim3(D_IN / 64, D_OUT / 64), 256>>>(scales, U, Dm, Q);
    gemm_kernel<<<(N_TOK / BM) * (D_OUT / BN), THREADS, SMEM_TOTAL>>>(out);
}

// round 7
// speedup vs baseline: 1.1747x; 1.0377x over previous
#include <cuda_runtime.h>
#include <cuda_fp16.h>
#include <cstdint>

#define N_TOK 8192
#define D_IN  4096
#define D_OUT 4096
#define RANK  64
#define D_PAD 4160            // D_IN + RANK

#define BM 128
#define BN 256
#define BK 64
#define NCHUNK (D_PAD / BK)   // 65
#define STAGES 4
#define THREADS 512

#define A_TILE_BYTES (BM * BK * 2)          // 16384
#define B_TILE_BYTES (BN * BK * 2)          // 32768
#define STAGE_BYTES (A_TILE_BYTES + B_TILE_BYTES)  // 49152
#define SMEM_TOTAL (STAGES * STAGE_BYTES)   // 196608

// Scratch via __device__ globals (runtime allocation is forbidden)
__device__ __half g_A[(size_t)N_TOK * D_PAD];   // [x | x@D^T] fp16   68 MB
__device__ __half g_B[(size_t)D_OUT * D_PAD];   // [Q*s | U]  fp16    34 MB
__device__ __half g_D[(size_t)RANK * D_IN];     // fp16(D)           0.5 MB

// ---------------- PTX helpers ----------------
__device__ __forceinline__ uint32_t smem_u32(const void* p) {
    uint32_t a;
    asm("{ .reg .u64 t; cvta.to.shared.u64 t, %1; cvt.u32.u64 %0, t; }" : "=r"(a) : "l"(p));
    return a;
}
__device__ __forceinline__ void cp16(uint32_t saddr, const void* g) {
    asm volatile("cp.async.cg.shared.global [%0], [%1], 16;" :: "r"(saddr), "l"(g));
}
#define CP_COMMIT() asm volatile("cp.async.commit_group;" ::: "memory")
#define CP_WAIT2()  asm volatile("cp.async.wait_group 2;" ::: "memory")

__device__ __forceinline__ void ldm_x4(uint32_t& r0, uint32_t& r1, uint32_t& r2, uint32_t& r3,
                                       uint32_t addr) {
    asm volatile("ldmatrix.sync.aligned.m8n8.x4.shared.b16 {%0,%1,%2,%3}, [%4];"
                 : "=r"(r0), "=r"(r1), "=r"(r2), "=r"(r3) : "r"(addr));
}
__device__ __forceinline__ void mma16816(float* d, const uint32_t* a, const uint32_t* b) {
    asm volatile(
        "mma.sync.aligned.m16n8k16.row.col.f32.f16.f16.f32 "
        "{%0,%1,%2,%3}, {%4,%5,%6,%7}, {%8,%9}, {%0,%1,%2,%3};"
        : "+f"(d[0]), "+f"(d[1]), "+f"(d[2]), "+f"(d[3])
        : "r"(a[0]), "r"(a[1]), "r"(a[2]), "r"(a[3]), "r"(b[0]), "r"(b[1]));
}

// ---------------- prep kernels ----------------

// x (fp32) -> g_A cols [0,4096) fp16; 8 floats/thread; 2 blocks per row
__global__ void __launch_bounds__(256) prep_a_kernel(const float* __restrict__ x) {
    int row = blockIdx.x >> 1;
    int col = ((blockIdx.x & 1) << 11) + threadIdx.x * 8;
    const float* src = x + (size_t)row * D_IN + col;
    float4 v0 = *reinterpret_cast<const float4*>(src);
    float4 v1 = *reinterpret_cast<const float4*>(src + 4);
    __half2 hv[4];
    hv[0] = __floats2half2_rn(v0.x, v0.y);
    hv[1] = __floats2half2_rn(v0.z, v0.w);
    hv[2] = __floats2half2_rn(v1.x, v1.y);
    hv[3] = __floats2half2_rn(v1.z, v1.w);
    *reinterpret_cast<uint4*>(g_A + (size_t)row * D_PAD + col) = *reinterpret_cast<uint4*>(hv);
}

// D (fp32 [64,4096]) -> g_D fp16
__global__ void __launch_bounds__(256) conv_d_kernel(const float* __restrict__ Dm) {
    size_t i = (size_t)blockIdx.x * 1024 + threadIdx.x * 4;
    float4 v = *reinterpret_cast<const float4*>(Dm + i);
    __half2 h0 = __floats2half2_rn(v.x, v.y);
    __half2 h1 = __floats2half2_rn(v.z, v.w);
    uint2 st;
    st.x = *reinterpret_cast<uint32_t*>(&h0);
    st.y = *reinterpret_cast<uint32_t*>(&h1);
    *reinterpret_cast<uint2*>(g_D + i) = st;
}

// U (fp32 [4096,64]) -> g_B cols [4096,4160) fp16
__global__ void __launch_bounds__(256) copy_u_kernel(const float* __restrict__ U) {
    size_t i = (size_t)blockIdx.x * 512 + threadIdx.x * 2;  // element pairs
    int o = (int)(i >> 6);
    int r = (int)(i & 63);
    float2 v = *reinterpret_cast<const float2*>(U + i);
    __half2 h = __floats2half2_rn(v.x, v.y);
    *reinterpret_cast<__half2*>(g_B + (size_t)o * D_PAD + D_IN + r) = h;
}

// pure dequant: g_B[o, i] = fp16(Q[o,i] * scales[o]); 8 elems/thread; 2 blocks/row
__global__ void __launch_bounds__(256) prep_w_kernel(
    const float* __restrict__ scales, const int* __restrict__ Q)
{
    int o = blockIdx.x >> 1;
    int col = ((blockIdx.x & 1) << 11) + threadIdx.x * 8;
    float sc = scales[o];
    const int* src = Q + (size_t)o * D_IN + col;
    int4 q0 = *reinterpret_cast<const int4*>(src);
    int4 q1 = *reinterpret_cast<const int4*>(src + 4);
    __half2 hv[4];
    hv[0] = __floats2half2_rn((float)q0.x * sc, (float)q0.y * sc);
    hv[1] = __floats2half2_rn((float)q0.z * sc, (float)q0.w * sc);
    hv[2] = __floats2half2_rn((float)q1.x * sc, (float)q1.y * sc);
    hv[3] = __floats2half2_rn((float)q1.z * sc, (float)q1.w * sc);
    *reinterpret_cast<uint4*>(g_B + (size_t)o * D_PAD + col) = *reinterpret_cast<uint4*>(hv);
}

// ---------------- adapter GEMM: T = x @ D^T  -> g_A cols [4096,4160) ----------------
// M=8192, N=64, K=4096. BM=64, BN=64, BK=64, 128 threads (4 warps 2x2, warp 32x32).
#define AD_STAGE_BYTES (2 * 64 * 128)        // A 8KB + B 8KB
#define AD_SMEM (STAGES * AD_STAGE_BYTES)    // 65536
__global__ void __launch_bounds__(128, 1) adapter_kernel() {
    extern __shared__ char smem[];
    uint32_t sbase = smem_u32(smem);
    int tid = threadIdx.x;
    int wid = tid >> 5;
    int lane = tid & 31;
    int m0 = blockIdx.x * 64;
    int wm = wid & 1;   // 32-row half
    int wn = wid >> 1;  // 32-col half

    auto load_stage = [&](int s, int c) {
        uint32_t st = sbase + s * AD_STAGE_BYTES;
        int k0 = c * BK;
#pragma unroll
        for (int j = 0; j < 4; ++j) {  // A: 512 chunks
            int t = tid + j * 128;
            int row = t >> 3, seg = t & 7;
            uint32_t so = (uint32_t)(row * 128 + ((seg ^ (row & 7)) << 4));
            cp16(st + so, g_A + (size_t)(m0 + row) * D_PAD + k0 + seg * 8);
        }
#pragma unroll
        for (int j = 0; j < 4; ++j) {  // B (D): 512 chunks
            int t = tid + j * 128;
            int row = t >> 3, seg = t & 7;
            uint32_t so = (uint32_t)(row * 128 + ((seg ^ (row & 7)) << 4));
            cp16(st + 8192 + so, g_D + (size_t)row * D_IN + k0 + seg * 8);
        }
    };

#pragma unroll
    for (int s = 0; s < STAGES - 1; ++s) { load_stage(s, s); CP_COMMIT(); }

    float acc[2][4][4] = {};
    int a_row_base = wm * 32 + (lane & 15);
    int b_row_base = wn * 32 + (lane & 15);
    int hi = lane >> 4;

    for (int c = 0; c < 64; ++c) {
        CP_WAIT2();
        __syncthreads();
        if (c + STAGES - 1 < 64) load_stage((c + STAGES - 1) & (STAGES - 1), c + STAGES - 1);
        CP_COMMIT();

        uint32_t stA = sbase + (c & (STAGES - 1)) * AD_STAGE_BYTES;
        uint32_t stB = stA + 8192;
#pragma unroll
        for (int kt = 0; kt < 4; ++kt) {
            uint32_t af[2][4];
#pragma unroll
            for (int mi = 0; mi < 2; ++mi) {
                int row = a_row_base + mi * 16;
                uint32_t chunk = (uint32_t)((kt * 2 + hi) ^ (row & 7));
                ldm_x4(af[mi][0], af[mi][1], af[mi][2], af[mi][3],
                       stA + (uint32_t)row * 128 + (chunk << 4));
            }
            uint32_t bf[4][2];
#pragma unroll
            for (int nj = 0; nj < 2; ++nj) {
                int row = b_row_base + nj * 16;
                uint32_t chunk = (uint32_t)((kt * 2 + hi) ^ (row & 7));
                uint32_t r0, r1, r2, r3;
                ldm_x4(r0, r1, r2, r3, stB + (uint32_t)row * 128 + (chunk << 4));
                bf[nj * 2][0] = r0; bf[nj * 2][1] = r2;
                bf[nj * 2 + 1][0] = r1; bf[nj * 2 + 1][1] = r3;
            }
#pragma unroll
            for (int mi = 0; mi < 2; ++mi)
#pragma unroll
                for (int ni = 0; ni < 4; ++ni)
                    mma16816(acc[mi][ni], af[mi], bf[ni]);
        }
    }

    // store fp16 into g_A cols [4096, 4160)
    int row0 = m0 + wm * 32 + (lane >> 2);
    int colb = wn * 32 + (lane & 3) * 2;
#pragma unroll
    for (int mi = 0; mi < 2; ++mi) {
#pragma unroll
        for (int ni = 0; ni < 4; ++ni) {
            __half2 h0 = __floats2half2_rn(acc[mi][ni][0], acc[mi][ni][1]);
            __half2 h1 = __floats2half2_rn(acc[mi][ni][2], acc[mi][ni][3]);
            *reinterpret_cast<__half2*>(
                g_A + (size_t)(row0 + mi * 16) * D_PAD + D_IN + colb + ni * 8) = h0;
            *reinterpret_cast<__half2*>(
                g_A + (size_t)(row0 + mi * 16 + 8) * D_PAD + D_IN + colb + ni * 8) = h1;
        }
    }
}

// ---------------- main GEMM ----------------
// out[m,n] = sum_k g_A[m,k] * g_B[n,k] over K=4160; fp16 in, fp32 accum.
// BM=128, BN=256, BK=64, 4-stage cp.async, mma.sync m16n8k16.
// 16 warps in 4x4; each warp owns a 32x64 tile.
__global__ void __launch_bounds__(THREADS, 1) gemm_kernel(float* __restrict__ out) {
    extern __shared__ char smem[];
    uint32_t sbase = smem_u32(smem);
    int tid = threadIdx.x;
    int wid = tid >> 5;
    int lane = tid & 31;

    int bx = blockIdx.x;
    int band = bx >> 8;
    int r = bx & 255;
    int n_tile = r >> 4;
    int m_tile = (band << 4) + (r & 15);
    int m0 = m_tile * BM;
    int n0 = n_tile * BN;

    int wm = wid & 3;
    int wn = wid >> 2;

    auto load_stage = [&](int s, int c) {
        uint32_t st = sbase + s * STAGE_BYTES;
        int k0 = c * BK;
#pragma unroll
        for (int j = 0; j < 2; ++j) {
            int t = tid + j * THREADS;
            int row = t >> 3, seg = t & 7;
            uint32_t so = (uint32_t)(row * 128 + ((seg ^ (row & 7)) << 4));
            cp16(st + so, g_A + (size_t)(m0 + row) * D_PAD + k0 + seg * 8);
        }
#pragma unroll
        for (int j = 0; j < 4; ++j) {
            int t = tid + j * THREADS;
            int row = t >> 3, seg = t & 7;
            uint32_t so = (uint32_t)(row * 128 + ((seg ^ (row & 7)) << 4));
            cp16(st + A_TILE_BYTES + so, g_B + (size_t)(n0 + row) * D_PAD + k0 + seg * 8);
        }
    };

#pragma unroll
    for (int s = 0; s < STAGES - 1; ++s) { load_stage(s, s); CP_COMMIT(); }

    float acc[2][8][4] = {};

    int a_row_base = wm * 32 + (lane & 15);
    int b_row_base = wn * 64 + (lane & 15);
    int hi = lane >> 4;

    for (int c = 0; c < NCHUNK; ++c) {
        CP_WAIT2();
        __syncthreads();
        if (c + STAGES - 1 < NCHUNK) load_stage((c + STAGES - 1) & (STAGES - 1), c + STAGES - 1);
        CP_COMMIT();

        uint32_t stA = sbase + (c & (STAGES - 1)) * STAGE_BYTES;
        uint32_t stB = stA + A_TILE_BYTES;

#pragma unroll
        for (int kt = 0; kt < 4; ++kt) {
            uint32_t af[2][4];
#pragma unroll
            for (int mi = 0; mi < 2; ++mi) {
                int row = a_row_base + mi * 16;
                uint32_t chunk = (uint32_t)((kt * 2 + hi) ^ (row & 7));
                ldm_x4(af[mi][0], af[mi][1], af[mi][2], af[mi][3],
                       stA + (uint32_t)row * 128 + (chunk << 4));
            }
            uint32_t bf[8][2];
#pragma unroll
            for (int nj = 0; nj < 4; ++nj) {
                int row = b_row_base + nj * 16;
                uint32_t chunk = (uint32_t)((kt * 2 + hi) ^ (row & 7));
                uint32_t r0, r1, r2, r3;
                ldm_x4(r0, r1, r2, r3, stB + (uint32_t)row * 128 + (chunk << 4));
                bf[nj * 2][0] = r0; bf[nj * 2][1] = r2;
                bf[nj * 2 + 1][0] = r1; bf[nj * 2 + 1][1] = r3;
            }
#pragma unroll
            for (int mi = 0; mi < 2; ++mi)
#pragma unroll
                for (int ni = 0; ni < 8; ++ni)
                    mma16816(acc[mi][ni], af[mi], bf[ni]);
        }
    }

    // Epilogue
    {
        int row0 = m0 + wm * 32 + (lane >> 2);
        int colb = n0 + wn * 64 + (lane & 3) * 2;
#pragma unroll
        for (int mi = 0; mi < 2; ++mi) {
#pragma unroll
            for (int ni = 0; ni < 8; ++ni) {
                float* p0 = out + (size_t)(row0 + mi * 16) * D_OUT + colb + ni * 8;
                float* p1 = out + (size_t)(row0 + mi * 16 + 8) * D_OUT + colb + ni * 8;
                float2 v0 = {acc[mi][ni][0], acc[mi][ni][1]};
                float2 v1 = {acc[mi][ni][2], acc[mi][ni][3]};
                *reinterpret_cast<float2*>(p0) = v0;
                *reinterpret_cast<float2*>(p1) = v1;
            }
        }
    }
}

// ---------------- launch ----------------
extern "C" void kernel_launch(void* const* d_in, const int* in_sizes, int n_in,
                              void* d_out, int out_size) {
    const float* x      = (const float*)d_in[0];
    const float* scales = (const float*)d_in[1];
    const float* U      = (const float*)d_in[2];
    const float* Dm     = (const float*)d_in[3];
    const int*   Q      = (const int*)d_in[4];
    float* out = (float*)d_out;

    cudaFuncSetAttribute(gemm_kernel, cudaFuncAttributeMaxDynamicSharedMemorySize, SMEM_TOTAL);
    cudaFuncSetAttribute(adapter_kernel, cudaFuncAttributeMaxDynamicSharedMemorySize, AD_SMEM);

    prep_a_kernel<<<N_TOK * 2, 256>>>(x);
    conv_d_kernel<<<(RANK * D_IN) / 1024, 256>>>(Dm);
    adapter_kernel<<<N_TOK / 64, 128, AD_SMEM>>>();
    prep_w_kernel<<<D_OUT * 2, 256>>>(scales, Q);
    copy_u_kernel<<<(D_OUT * RANK) / 512, 256>>>(U);
    gemm_kernel<<<(N_TOK / BM) * (D_OUT / BN), THREADS, SMEM_TOTAL>>>(out);
}